// round 16
// baseline (speedup 1.0000x reference)
#include <cuda_runtime.h>
#include <math.h>
#include <stdint.h>

// Problem constants (fixed by the dataset)
#define NN      4096
#define MM      2048
#define DVV     3
#define DCC     6
#define EE      (NN*DVV)      // 12288
#define BB      2048
#define NITER   5
#define THREADS 512
#define CN_T    (MM/THREADS)  // 4 CN tasks per thread (each covers 2 rows)
#define VN_T    (NN/THREADS)  // 8 VN tasks per thread

// SMEM: SoA msg planes: 3 planes of NN packed f32x2 = 98304 B -> 2 CTAs/SM
#define SMEM_BYTES (EE*8)

typedef unsigned long long ull;

// ---------------------------------------------------------------------------
// MUFU + pack helpers
// ---------------------------------------------------------------------------
__device__ __forceinline__ float ex2a(float x){ float r; asm("ex2.approx.ftz.f32 %0, %1;" : "=f"(r) : "f"(x)); return r; }
__device__ __forceinline__ float lg2a(float x){ float r; asm("lg2.approx.ftz.f32 %0, %1;" : "=f"(r) : "f"(x)); return r; }
__device__ __forceinline__ float rcpa(float x){ float r; asm("rcp.approx.ftz.f32 %0, %1;" : "=f"(r) : "f"(x)); return r; }
__device__ __forceinline__ ull  pk2(float a, float b){ ull r; asm("mov.b64 %0, {%1, %2};" : "=l"(r) : "f"(a), "f"(b)); return r; }
__device__ __forceinline__ void upk2(ull x, float& a, float& b){ asm("mov.b64 {%0, %1}, %2;" : "=f"(a), "=f"(b) : "l"(x)); }
__device__ __forceinline__ ull  fma2(ull a, ull b, ull c){ ull r; asm("fma.rn.f32x2 %0, %1, %2, %3;" : "=l"(r) : "l"(a), "l"(b), "l"(c)); return r; }
__device__ __forceinline__ ull  mul2(ull a, ull b){ ull r; asm("mul.rn.f32x2 %0, %1, %2;" : "=l"(r) : "l"(a), "l"(b)); return r; }
__device__ __forceinline__ ull  add2(ull a, ull b){ ull r; asm("add.rn.f32x2 %0, %1, %2;" : "=l"(r) : "l"(a), "l"(b)); return r; }

#define LOG2E_F 1.4426950408889634f
#define LN2_F   0.6931471805599453f
#define MAGMAX  16.635532f            /* 2*atanh(float(1-1e-7)): emulates CLIP    */
#define UMAX_F  0.99999988f           /* 1-2^-23: keeps 1-u and products nonzero  */

// ---------------------------------------------------------------------------
// Persistent scratch (static globals: no runtime allocation)
// ---------------------------------------------------------------------------
__device__ int   g_cnt[MM];
__device__ int   g_tmp[EE];        // g_tmp[m*6+slot] = edge id (atomic order)
__device__ uint4 g_idx[MM];        // per CN: 6 x u16 plane-major edge indices (16B)
__device__ float g_wp[EE];         // plane-major weights: g_wp[(e%3)*NN + e/3] = w[e]

// ---------------------------------------------------------------------------
// Prep kernels (deterministic)
// ---------------------------------------------------------------------------
__global__ void prep_zero()
{
    int i = blockIdx.x * blockDim.x + threadIdx.x;
    if (i < MM) g_cnt[i] = 0;
}

__global__ void prep_fill(const int* __restrict__ cn_idx,
                          const float* __restrict__ w)
{
    int e = blockIdx.x * blockDim.x + threadIdx.x;
    if (e < EE) {
        int m = cn_idx[e];
        int p = atomicAdd(&g_cnt[m], 1);
        g_tmp[m * DCC + p] = e;
        g_wp[(e % DVV) * NN + (e / DVV)] = w[e];   // plane-major weights
    }
}

__global__ void prep_pack()
{
    int m = blockIdx.x * blockDim.x + threadIdx.x;
    if (m >= MM) return;
    int a[DCC];
#pragma unroll
    for (int j = 0; j < DCC; j++) a[j] = g_tmp[m * DCC + j];
    // sort ascending -> deterministic per-CN edge set
#pragma unroll
    for (int i = 0; i < DCC - 1; i++)
#pragma unroll
        for (int j = 0; j < DCC - 1 - i; j++)
            if (a[j] > a[j + 1]) { int t = a[j]; a[j] = a[j + 1]; a[j + 1] = t; }

    // plane-major u16 indices: i = (e%3)*NN + e/3 (< 12288, fits u16)
    unsigned i0 = (unsigned)((a[0] % DVV) * NN + a[0] / DVV);
    unsigned i1 = (unsigned)((a[1] % DVV) * NN + a[1] / DVV);
    unsigned i2 = (unsigned)((a[2] % DVV) * NN + a[2] / DVV);
    unsigned i3 = (unsigned)((a[3] % DVV) * NN + a[3] / DVV);
    unsigned i4 = (unsigned)((a[4] % DVV) * NN + a[4] / DVV);
    unsigned i5 = (unsigned)((a[5] % DVV) * NN + a[5] / DVV);
    uint4 q;
    q.x = i0 | (i1 << 16);
    q.y = i2 | (i3 << 16);
    q.z = i4 | (i5 << 16);
    q.w = 0;
    g_idx[m] = q;
}

// Conflict-aware round assignment: for each warp-group of 32 consecutive CNs,
// greedily place each lane's 6 edges into 6 rounds so that within each round
// the 32 accesses spread over the 16 smem bank-pair bins (8B entries: bin =
// idx mod 16). Products/signs are order-independent, so this only changes
// FP rounding at the ~1e-7 level.
__global__ void prep_assign()
{
    int g = blockIdx.x * blockDim.x + threadIdx.x;
    if (g >= MM / 32) return;

    unsigned short idx[32][6];
    for (int l = 0; l < 32; l++) {
        uint4 q = g_idx[g * 32 + l];
        idx[l][0] = (unsigned short)(q.x & 0xFFFFu);
        idx[l][1] = (unsigned short)(q.x >> 16);
        idx[l][2] = (unsigned short)(q.y & 0xFFFFu);
        idx[l][3] = (unsigned short)(q.y >> 16);
        idx[l][4] = (unsigned short)(q.z & 0xFFFFu);
        idx[l][5] = (unsigned short)(q.z >> 16);
    }
    unsigned used[32];
    for (int l = 0; l < 32; l++) used[l] = 0u;
    unsigned short outp[32][6];
    for (int j = 0; j < 6; j++) {
        int load[16];
        for (int b = 0; b < 16; b++) load[b] = 0;
        for (int l = 0; l < 32; l++) {
            int be = -1, bb = 0, bl = 1 << 30;
            for (int e = 0; e < 6; e++) {
                if (used[l] & (1u << e)) continue;
                int b = idx[l][e] & 15;
                if (load[b] < bl) { bl = load[b]; be = e; bb = b; }
            }
            used[l] |= 1u << be;
            load[bb]++;
            outp[l][j] = idx[l][be];
        }
    }
    for (int l = 0; l < 32; l++) {
        uint4 q;
        q.x = (unsigned)outp[l][0] | ((unsigned)outp[l][1] << 16);
        q.y = (unsigned)outp[l][2] | ((unsigned)outp[l][3] << 16);
        q.z = (unsigned)outp[l][4] | ((unsigned)outp[l][5] << 16);
        q.w = 0;
        g_idx[g * 32 + l] = q;
    }
}

// ---------------------------------------------------------------------------
// Main BP kernel: one CTA per 2 batch rows, SoA msg planes (packed f32x2) in
// SMEM holding PRE-WEIGHTED vn messages; product-domain CN update with 16B/CN
// descriptors in conflict-minimized round order; llr pairs in regs. 2 CTAs/SM.
// ---------------------------------------------------------------------------
__global__ __launch_bounds__(THREADS, 2)
void bp_kernel(const float* __restrict__ noise_r,
               float* __restrict__ out)
{
    extern __shared__ ull smem8[];
    ull* P0 = smem8;            // plane 0: NN packed pairs
    ull* P1 = smem8 + NN;       // plane 1
    ull* P2 = smem8 + 2 * NN;   // plane 2

    const int tid  = threadIdx.x;
    const int rowA = blockIdx.x * 2;
    const float* nra = noise_r + (size_t)rowA * NN;
    const float* nrb = nra + NN;

    const float NO_F = 0.3981071705534972f;   // 10^-0.4
    const float NSTD = 0.44615420f;           // sqrtf(no/2) in f32
    const ull   NEG1 = pk2(-1.0f, -1.0f);

    // llr lives in registers: one packed pair per owned VN
    ull llr_r[VN_T];

    // ---- init: llr (regs) + PRE-WEIGHTED msg planes (coalesced) ----
#pragma unroll
    for (int k = 0; k < VN_T; ++k) {
        const int v = tid + k * THREADS;
        float la = (4.0f * (1.0f + NSTD * nra[v])) / NO_F;
        float lb = (4.0f * (1.0f + NSTD * nrb[v])) / NO_F;
        ull l2 = pk2(la, lb);
        llr_r[k] = l2;
        float w0 = __ldg(&g_wp[0 * NN + v]);
        float w1 = __ldg(&g_wp[1 * NN + v]);
        float w2 = __ldg(&g_wp[2 * NN + v]);
        P0[v] = mul2(l2, pk2(w0, w0));
        P1[v] = mul2(l2, pk2(w1, w1));
        P2[v] = mul2(l2, pk2(w2, w2));
    }
    __syncthreads();

    for (int it = 0; it < NITER; ++it) {
        // ---- check-node pass: product-domain tanh BP, both rows ----
#pragma unroll
        for (int k = 0; k < CN_T; ++k) {
            const int m = tid + k * THREADS;
            const uint4 q = __ldg(&g_idx[m]);   // 16B/CN: 6 x u16 indices

            unsigned off[6];
            off[0] = (q.x & 0xFFFFu) * 8;  off[1] = (q.x >> 16) * 8;
            off[2] = (q.y & 0xFFFFu) * 8;  off[3] = (q.y >> 16) * 8;
            off[4] = (q.z & 0xFFFFu) * 8;  off[5] = (q.z >> 16) * 8;

            float    ua[6], ub[6];
            unsigned sl = 0u, sh = 0u;   // per-row sign bitmasks (bit j)
            float Aa = 1.0f, Ba = 1.0f;  // prod (1-u), prod (1+u), row A
            float Ab = 1.0f, Bb = 1.0f;  // row B
#pragma unroll
            for (int j = 0; j < 6; ++j) {
                ull mm = *reinterpret_cast<const ull*>(
                             reinterpret_cast<const char*>(smem8) + off[j]);
                float xl, xh; upk2(mm, xl, xh);   // already weighted
                sl |= (__float_as_uint(xl) >> 31) << j;
                sh |= (__float_as_uint(xh) >> 31) << j;
                // u = e^{-|x|}  (so tanh(|x|/2) = (1-u)/(1+u))
                float va = ex2a(fabsf(xl) * -LOG2E_F);
                float vb = ex2a(fabsf(xh) * -LOG2E_F);
                va = fminf(va, UMAX_F);
                vb = fminf(vb, UMAX_F);
                ua[j] = va;  ub[j] = vb;
                Aa = fmaf(Aa, -va, Aa);  Ba = fmaf(Ba, va, Ba);
                Ab = fmaf(Ab, -vb, Ab);  Bb = fmaf(Bb, vb, Bb);
            }
            // w = prod tanh(|x_j|/2) = e^{-S}
            const float wa_ = Aa * rcpa(Ba);
            const float wb_ = Ab * rcpa(Bb);
            const float c1a = 1.0f + wa_, c2a = wa_ - 1.0f;
            const float c1b = 1.0f + wb_, c2b = wb_ - 1.0f;
            const unsigned pl = __popc(sl) & 1u;
            const unsigned ph = __popc(sh) & 1u;
#pragma unroll
            for (int j = 0; j < 6; ++j) {
                float va = ua[j], vb = ub[j];
                // z = w*(1+u)/(1-u);  mag = ln((1+z)/(1-z)) = 2*atanh(z)
                // num = (1-u) + w(1+u) = c1 + u*c2 ; den = (1-u) - w(1+u) = -c2 - u*c1
                float numa = fmaf(va,  c2a, c1a);
                float dena = fmaxf(fmaf(va, -c1a, -c2a), 1e-30f);
                float numb = fmaf(vb,  c2b, c1b);
                float denb = fmaxf(fmaf(vb, -c1b, -c2b), 1e-30f);
                float maga = fminf((lg2a(numa) - lg2a(dena)) * LN2_F, MAGMAX);
                float magb = fminf((lg2a(numb) - lg2a(denb)) * LN2_F, MAGMAX);
                unsigned rl = __float_as_uint(maga) | ((pl ^ ((sl >> j) & 1u)) << 31);
                unsigned rh = __float_as_uint(magb) | ((ph ^ ((sh >> j) & 1u)) << 31);
                *reinterpret_cast<ull*>(reinterpret_cast<char*>(smem8) + off[j]) =
                    pk2(__uint_as_float(rl), __uint_as_float(rh));
            }
        }
        __syncthreads();

        // ---- variable-node pass: coalesced SoA planes; re-weight on store ----
        const bool last = (it == NITER - 1);
#pragma unroll
        for (int k = 0; k < VN_T; ++k) {
            const int v = tid + k * THREADS;
            ull m0 = P0[v];      // unweighted msg_cn from the CN pass
            ull m1 = P1[v];
            ull m2 = P2[v];
            ull s  = add2(add2(m0, m1), m2);
            ull lt = add2(llr_r[k], s);
            if (last) {
                float a, b; upk2(lt, a, b);
                out[(size_t)rowA * NN + v]       = a;
                out[(size_t)(rowA + 1) * NN + v] = b;
            } else {
                float w0 = __ldg(&g_wp[0 * NN + v]);
                float w1 = __ldg(&g_wp[1 * NN + v]);
                float w2 = __ldg(&g_wp[2 * NN + v]);
                P0[v] = mul2(fma2(m0, NEG1, lt), pk2(w0, w0));
                P1[v] = mul2(fma2(m1, NEG1, lt), pk2(w1, w1));
                P2[v] = mul2(fma2(m2, NEG1, lt), pk2(w2, w2));
            }
        }
        __syncthreads();
    }
}

// ---------------------------------------------------------------------------
// Launch
// ---------------------------------------------------------------------------
extern "C" void kernel_launch(void* const* d_in, const int* in_sizes, int n_in,
                              void* d_out, int out_size)
{
    const float* noise_r = (const float*)d_in[0];
    // d_in[1] = noise_i (unused by the reference)
    const float* weights = (const float*)d_in[2];
    // d_in[3] = vn_idx (structural: e/3)
    const int*   cn_idx  = (const int*)d_in[4];
    float* out = (float*)d_out;

    (void)in_sizes; (void)n_in; (void)out_size;

    cudaFuncSetAttribute(bp_kernel, cudaFuncAttributeMaxDynamicSharedMemorySize, SMEM_BYTES);

    prep_zero<<<(MM + 255) / 256, 256>>>();
    prep_fill<<<(EE + 255) / 256, 256>>>(cn_idx, weights);
    prep_pack<<<(MM + 255) / 256, 256>>>();
    prep_assign<<<1, MM / 32>>>();

    bp_kernel<<<BB / 2, THREADS, SMEM_BYTES>>>(noise_r, out);
}

// round 17
// speedup vs baseline: 1.2809x; 1.2809x over previous
#include <cuda_runtime.h>
#include <cuda_fp16.h>
#include <math.h>
#include <stdint.h>

// Problem constants (fixed by the dataset)
#define NN      4096
#define MM      2048
#define DVV     3
#define DCC     6
#define EE      (NN*DVV)      // 12288
#define BB      2048
#define NITER   5
#define THREADS 512
#define CN_T    (MM/THREADS)  // 4 CN tasks per thread (each covers 2 rows)
#define VN_T    (NN/THREADS)  // 8 VN tasks per thread

// SMEM: SoA msg planes: 3 planes of NN fp16x2 (4B) = 49152 B -> 2 CTAs/SM
#define SMEM_BYTES (EE*4)

#define LOG2E_F 1.4426950408889634f
#define LN2_F   0.6931471805599453f
#define MAGMAX  16.635532f            /* 2*atanh(float(1-1e-7)): emulates CLIP    */
#define UMAX_F  0.99999988f           /* 1-2^-23: keeps 1-u and products nonzero  */

// ---------------------------------------------------------------------------
// MUFU + fp16 pack helpers
// ---------------------------------------------------------------------------
__device__ __forceinline__ float ex2a(float x){ float r; asm("ex2.approx.ftz.f32 %0, %1;" : "=f"(r) : "f"(x)); return r; }
__device__ __forceinline__ float lg2a(float x){ float r; asm("lg2.approx.ftz.f32 %0, %1;" : "=f"(r) : "f"(x)); return r; }
__device__ __forceinline__ float rcpa(float x){ float r; asm("rcp.approx.ftz.f32 %0, %1;" : "=f"(r) : "f"(x)); return r; }

__device__ __forceinline__ float2 h2_unpack(unsigned u)
{
    __half2 h = *reinterpret_cast<__half2*>(&u);
    return __half22float2(h);
}
__device__ __forceinline__ unsigned h2_pack(float a, float b)
{
    __half2 h = __float22half2_rn(make_float2(a, b));
    return *reinterpret_cast<unsigned*>(&h);
}

// ---------------------------------------------------------------------------
// Persistent scratch (static globals: no runtime allocation)
// ---------------------------------------------------------------------------
__device__ int   g_cnt[MM];
__device__ int   g_tmp[EE];        // g_tmp[m*6+slot] = edge id (atomic order)
__device__ uint4 g_idx[MM];        // per CN: 6 x u16 plane-major edge indices (16B)
__device__ float g_wp[EE];         // plane-major weights: g_wp[(e%3)*NN + e/3] = w[e]

// ---------------------------------------------------------------------------
// Prep kernels (deterministic after the sort)
// ---------------------------------------------------------------------------
__global__ void prep_zero()
{
    int i = blockIdx.x * blockDim.x + threadIdx.x;
    if (i < MM) g_cnt[i] = 0;
}

__global__ void prep_fill(const int* __restrict__ cn_idx,
                          const float* __restrict__ w)
{
    int e = blockIdx.x * blockDim.x + threadIdx.x;
    if (e < EE) {
        int m = cn_idx[e];
        int p = atomicAdd(&g_cnt[m], 1);
        g_tmp[m * DCC + p] = e;
        g_wp[(e % DVV) * NN + (e / DVV)] = w[e];   // plane-major weights
    }
}

__global__ void prep_pack()
{
    int m = blockIdx.x * blockDim.x + threadIdx.x;
    if (m >= MM) return;
    int a[DCC];
#pragma unroll
    for (int j = 0; j < DCC; j++) a[j] = g_tmp[m * DCC + j];
    // sort ascending -> deterministic per-CN edge set
#pragma unroll
    for (int i = 0; i < DCC - 1; i++)
#pragma unroll
        for (int j = 0; j < DCC - 1 - i; j++)
            if (a[j] > a[j + 1]) { int t = a[j]; a[j] = a[j + 1]; a[j + 1] = t; }

    // plane-major u16 indices: i = (e%3)*NN + e/3 (< 12288, fits u16)
    unsigned i0 = (unsigned)((a[0] % DVV) * NN + a[0] / DVV);
    unsigned i1 = (unsigned)((a[1] % DVV) * NN + a[1] / DVV);
    unsigned i2 = (unsigned)((a[2] % DVV) * NN + a[2] / DVV);
    unsigned i3 = (unsigned)((a[3] % DVV) * NN + a[3] / DVV);
    unsigned i4 = (unsigned)((a[4] % DVV) * NN + a[4] / DVV);
    unsigned i5 = (unsigned)((a[5] % DVV) * NN + a[5] / DVV);
    uint4 q;
    q.x = i0 | (i1 << 16);
    q.y = i2 | (i3 << 16);
    q.z = i4 | (i5 << 16);
    q.w = 0;
    g_idx[m] = q;
}

// ---------------------------------------------------------------------------
// Main BP kernel: one CTA per 2 batch rows. Messages stored PRE-WEIGHTED as
// fp16x2 (rows A,B) in 3 SoA planes (48KB smem); all arithmetic fp32;
// product-domain CN update; llr pairs fp32 in registers. 2 CTAs/SM.
// ---------------------------------------------------------------------------
__global__ __launch_bounds__(THREADS, 2)
void bp_kernel(const float* __restrict__ noise_r,
               float* __restrict__ out)
{
    extern __shared__ unsigned smem4[];
    unsigned* P0 = smem4;            // plane 0: NN fp16x2 entries
    unsigned* P1 = smem4 + NN;       // plane 1
    unsigned* P2 = smem4 + 2 * NN;   // plane 2

    const int tid  = threadIdx.x;
    const int rowA = blockIdx.x * 2;
    const float* nra = noise_r + (size_t)rowA * NN;
    const float* nrb = nra + NN;

    const float NO_F = 0.3981071705534972f;   // 10^-0.4
    const float NSTD = 0.44615420f;           // sqrtf(no/2) in f32

    // llr lives in fp32 registers: one value per row per owned VN
    float llA[VN_T], llB[VN_T];

    // ---- init: llr (regs) + PRE-WEIGHTED fp16x2 msg planes (coalesced) ----
#pragma unroll
    for (int k = 0; k < VN_T; ++k) {
        const int v = tid + k * THREADS;
        float la = (4.0f * (1.0f + NSTD * nra[v])) / NO_F;
        float lb = (4.0f * (1.0f + NSTD * nrb[v])) / NO_F;
        llA[k] = la;
        llB[k] = lb;
        float w0 = __ldg(&g_wp[0 * NN + v]);
        float w1 = __ldg(&g_wp[1 * NN + v]);
        float w2 = __ldg(&g_wp[2 * NN + v]);
        P0[v] = h2_pack(la * w0, lb * w0);
        P1[v] = h2_pack(la * w1, lb * w1);
        P2[v] = h2_pack(la * w2, lb * w2);
    }
    __syncthreads();

    for (int it = 0; it < NITER; ++it) {
        // ---- check-node pass: product-domain tanh BP, both rows ----
#pragma unroll
        for (int k = 0; k < CN_T; ++k) {
            const int m = tid + k * THREADS;
            const uint4 q = __ldg(&g_idx[m]);   // 16B/CN: 6 x u16 indices

            unsigned off[6];
            off[0] = (q.x & 0xFFFFu) * 4;  off[1] = (q.x >> 16) * 4;
            off[2] = (q.y & 0xFFFFu) * 4;  off[3] = (q.y >> 16) * 4;
            off[4] = (q.z & 0xFFFFu) * 4;  off[5] = (q.z >> 16) * 4;

            float    ua[6], ub[6];
            unsigned sl = 0u, sh = 0u;   // per-row sign bitmasks (bit j)
            float Aa = 1.0f, Ba = 1.0f;  // prod (1-u), prod (1+u), row A
            float Ab = 1.0f, Bb = 1.0f;  // row B
#pragma unroll
            for (int j = 0; j < 6; ++j) {
                unsigned mm = *reinterpret_cast<const unsigned*>(
                                  reinterpret_cast<const char*>(smem4) + off[j]);
                float2 x = h2_unpack(mm);          // already weighted
                sl |= (__float_as_uint(x.x) >> 31) << j;
                sh |= (__float_as_uint(x.y) >> 31) << j;
                // u = e^{-|x|}  (so tanh(|x|/2) = (1-u)/(1+u))
                float va = ex2a(fabsf(x.x) * -LOG2E_F);
                float vb = ex2a(fabsf(x.y) * -LOG2E_F);
                va = fminf(va, UMAX_F);
                vb = fminf(vb, UMAX_F);
                ua[j] = va;  ub[j] = vb;
                Aa = fmaf(Aa, -va, Aa);  Ba = fmaf(Ba, va, Ba);
                Ab = fmaf(Ab, -vb, Ab);  Bb = fmaf(Bb, vb, Bb);
            }
            // w = prod tanh(|x_j|/2) = e^{-S}
            const float wa_ = Aa * rcpa(Ba);
            const float wb_ = Ab * rcpa(Bb);
            const float c1a = 1.0f + wa_, c2a = wa_ - 1.0f;
            const float c1b = 1.0f + wb_, c2b = wb_ - 1.0f;
            const unsigned pl = __popc(sl) & 1u;
            const unsigned ph = __popc(sh) & 1u;
#pragma unroll
            for (int j = 0; j < 6; ++j) {
                float va = ua[j], vb = ub[j];
                // z = w*(1+u)/(1-u);  mag = ln((1+z)/(1-z)) = 2*atanh(z)
                // num = (1-u) + w(1+u) = c1 + u*c2 ; den = (1-u) - w(1+u) = -c2 - u*c1
                float numa = fmaf(va,  c2a, c1a);
                float dena = fmaxf(fmaf(va, -c1a, -c2a), 1e-30f);
                float numb = fmaf(vb,  c2b, c1b);
                float denb = fmaxf(fmaf(vb, -c1b, -c2b), 1e-30f);
                float maga = fminf((lg2a(numa) - lg2a(dena)) * LN2_F, MAGMAX);
                float magb = fminf((lg2a(numb) - lg2a(denb)) * LN2_F, MAGMAX);
                unsigned rl = __float_as_uint(maga) | ((pl ^ ((sl >> j) & 1u)) << 31);
                unsigned rh = __float_as_uint(magb) | ((ph ^ ((sh >> j) & 1u)) << 31);
                *reinterpret_cast<unsigned*>(reinterpret_cast<char*>(smem4) + off[j]) =
                    h2_pack(__uint_as_float(rl), __uint_as_float(rh));
            }
        }
        __syncthreads();

        // ---- variable-node pass: coalesced SoA planes; re-weight on store ----
        const bool last = (it == NITER - 1);
#pragma unroll
        for (int k = 0; k < VN_T; ++k) {
            const int v = tid + k * THREADS;
            float2 f0 = h2_unpack(P0[v]);   // unweighted msg_cn from CN pass
            float2 f1 = h2_unpack(P1[v]);
            float2 f2 = h2_unpack(P2[v]);
            float ltA = llA[k] + ((f0.x + f1.x) + f2.x);   // ascending edge order
            float ltB = llB[k] + ((f0.y + f1.y) + f2.y);
            if (last) {
                out[(size_t)rowA * NN + v]       = ltA;
                out[(size_t)(rowA + 1) * NN + v] = ltB;
            } else {
                float w0 = __ldg(&g_wp[0 * NN + v]);
                float w1 = __ldg(&g_wp[1 * NN + v]);
                float w2 = __ldg(&g_wp[2 * NN + v]);
                P0[v] = h2_pack((ltA - f0.x) * w0, (ltB - f0.y) * w0);
                P1[v] = h2_pack((ltA - f1.x) * w1, (ltB - f1.y) * w1);
                P2[v] = h2_pack((ltA - f2.x) * w2, (ltB - f2.y) * w2);
            }
        }
        __syncthreads();
    }
}

// ---------------------------------------------------------------------------
// Launch
// ---------------------------------------------------------------------------
extern "C" void kernel_launch(void* const* d_in, const int* in_sizes, int n_in,
                              void* d_out, int out_size)
{
    const float* noise_r = (const float*)d_in[0];
    // d_in[1] = noise_i (unused by the reference)
    const float* weights = (const float*)d_in[2];
    // d_in[3] = vn_idx (structural: e/3)
    const int*   cn_idx  = (const int*)d_in[4];
    float* out = (float*)d_out;

    (void)in_sizes; (void)n_in; (void)out_size;

    cudaFuncSetAttribute(bp_kernel, cudaFuncAttributeMaxDynamicSharedMemorySize, SMEM_BYTES);

    prep_zero<<<(MM + 255) / 256, 256>>>();
    prep_fill<<<(EE + 255) / 256, 256>>>(cn_idx, weights);
    prep_pack<<<(MM + 255) / 256, 256>>>();

    bp_kernel<<<BB / 2, THREADS, SMEM_BYTES>>>(noise_r, out);
}